// round 10
// baseline (speedup 1.0000x reference)
#include <cuda_runtime.h>

#define LL 1024
#define BB 4
#define NHID 128
#define NH 10
#define HD 10
#define DD 100
#define INV_SQRT_HD 0.31622776601683794f

typedef unsigned long long ull;

// Scratch (device globals: no allocation allowed)
static __device__ float qp_s[2][BB][DD][LL];                  // q partials (h-split)
static __device__ __align__(16) float E_s[BB][NH][LL];        // exp(t) (no max shift)
static __device__ __align__(16) float W_s[BB][NH][HD][LL];    // E * k
static __device__ float inv_s[BB][NH][LL];                    // 1/denom per row
// att in the reference's scrambled channel layout: att_flat[b][n*LL*HD + i*HD + d]
static __device__ float att_s[BB][DD * LL];
// packed edge mask: bit k of word w covers col w*32+k; flat [b][row][32 words]
static __device__ __align__(16) unsigned bmg[BB * LL * 32];

__device__ __forceinline__ void ffma2(ull &acc, ull a, ull b) {
    asm("fma.rn.f32x2 %0, %1, %2, %0;" : "+l"(acc) : "l"(a), "l"(b));
}
__device__ __forceinline__ ull fmul2(ull a, ull b) {
    ull r;
    asm("mul.rn.f32x2 %0, %1, %2;" : "=l"(r) : "l"(a), "l"(b));
    return r;
}
__device__ __forceinline__ float pairsum(ull a) {
    return __uint_as_float((unsigned)a) + __uint_as_float((unsigned)(a >> 32));
}

// ---------------------------------------------------------------------------
// Kernel 0: pack edge (4M int32) -> bitmask (128K words). Coalesced + ballot.
// ---------------------------------------------------------------------------
__global__ void __launch_bounds__(256) k0_pack(const int* __restrict__ edge) {
    unsigned t = blockIdx.x * 256 + threadIdx.x;   // 131072 threads
#pragma unroll
    for (int it = 0; it < 32; ++it) {
        unsigned g = it * 131072u + t;
        unsigned word = __ballot_sync(0xffffffffu, edge[g] != 0);
        if ((threadIdx.x & 31) == 0) bmg[g >> 5] = word;
    }
}

// ---------------------------------------------------------------------------
// Kernel 1: q partials. qp[hh][b][c][l] = sum_{h in hh-half} wq_w[c,h]*x[b,h,l]
// grid (32 l-tiles, 2 h-halves, B), 256 thr.
// dyn smem: xs[64][36] (9216B) + wsm[100][65] (26000B) = 35216B
// ---------------------------------------------------------------------------
__global__ void __launch_bounds__(256) k1_q(const float* __restrict__ x,
                                            const float* __restrict__ wq_w) {
    extern __shared__ __align__(16) char smem1[];
    float (*xs)[36]  = (float(*)[36])smem1;                  // [h][l]
    float (*wsm)[65] = (float(*)[65])(smem1 + 9216);         // [c][h] natural, odd pad

    int lt = blockIdx.x, hh = blockIdx.y, b = blockIdx.z;
    int tid = threadIdx.x;

    for (int idx = tid; idx < 512; idx += 256) {
        int h = idx >> 3, lq = idx & 7;
        float4 v = *(const float4*)&x[((size_t)(b * NHID + hh * 64 + h) * LL) + lt * 32 + lq * 4];
        *(float4*)&xs[h][lq * 4] = v;
    }
    for (int f = tid; f < 1600; f += 256) {
        int c = f >> 4, h4 = f & 15;
        float4 w = ((const float4*)wq_w)[c * 32 + hh * 16 + h4];
        wsm[c][h4 * 4 + 0] = w.x;
        wsm[c][h4 * 4 + 1] = w.y;
        wsm[c][h4 * 4 + 2] = w.z;
        wsm[c][h4 * 4 + 3] = w.w;
    }
    __syncthreads();

    int lg = tid >> 5, cg = tid & 31;
    int c0 = cg * 4, l0 = lg * 4;
    int c0c = (c0 > 96) ? 96 : c0;

    float acc[4][4];
#pragma unroll
    for (int i = 0; i < 4; i++)
#pragma unroll
        for (int j = 0; j < 4; j++) acc[i][j] = 0.f;

#pragma unroll 4
    for (int h = 0; h < 64; h++) {
        float wa[4];
#pragma unroll
        for (int i = 0; i < 4; i++) wa[i] = wsm[c0c + i][h];
        float4 xv = *(const float4*)&xs[h][l0];
        float xa[4] = {xv.x, xv.y, xv.z, xv.w};
#pragma unroll
        for (int i = 0; i < 4; i++)
#pragma unroll
            for (int j = 0; j < 4; j++) acc[i][j] += wa[i] * xa[j];
    }

#pragma unroll
    for (int i = 0; i < 4; i++) {
        int c = c0 + i;
        if (c < DD) {
            float4 o = make_float4(acc[i][0], acc[i][1], acc[i][2], acc[i][3]);
            *(float4*)&qp_s[hh][b][c][lt * 32 + l0] = o;
        }
    }
}

// ---------------------------------------------------------------------------
// Kernel 2: E/W. No max subtraction (shift-invariant; |t| small) -> parallel.
// grid (8, NH, B), 128 thr; thread = one l.
// ---------------------------------------------------------------------------
__global__ void __launch_bounds__(128) k2_ew(const float* __restrict__ wedge_w,
                                             const float* __restrict__ wq_b) {
    int n = blockIdx.y, b = blockIdx.z;
    int l = blockIdx.x * 128 + threadIdx.x;

    float qd[HD];
    float t = 0.f;
#pragma unroll
    for (int d = 0; d < HD; d++) {
        int c = n * HD + d;
        qd[d] = qp_s[0][b][c][l] + qp_s[1][b][c][l] + __ldg(&wq_b[c]);
        t += qd[d] * __ldg(&wedge_w[HD + d]);
    }
    t *= INV_SQRT_HD;

    float E = expf(t);
    E_s[b][n][l] = E;
#pragma unroll
    for (int d = 0; d < HD; d++) W_s[b][n][d][l] = E * qd[d];
}

// ---------------------------------------------------------------------------
// Kernel 3a: att + inv. Per (b, n, 128-row tile). 128 threads = 4 warps.
// Warp = col-quarter (256 cols); LANE OWNS FOUR ROWS (lane, +32, +64, +96),
// so every uniform E/W LDS.128 broadcast is amortized over 4 rows and each
// warp carries 44 independent FFMA2 chains (ILP saturates fma pipe at low
// occupancy). bm dead after pass 1 -> overlaid by part[].
// dyn smem: E(4096)+W(40960)+max(bm 16896, part 24576)=69632B
// ---------------------------------------------------------------------------
__global__ void __launch_bounds__(128) k3a_att(void) {
    extern __shared__ __align__(16) char smem3[];
    float* E_sm = (float*)smem3;                                   // [1024]
    float (*W_sm)[LL] = (float(*)[LL])(smem3 + 4096);              // [10][1024]
    unsigned (*bm)[33] = (unsigned(*)[33])(smem3 + 45056);         // [128][33]
    float (*part)[128][12] = (float(*)[128][12])(smem3 + 45056);   // [4][128][12] OVERLAY

    int n = blockIdx.x, tile = blockIdx.y, b = blockIdx.z;
    int tid = threadIdx.x, warp = tid >> 5, lane = tid & 31;
    int rowbase = tile * 128;

    for (int idx = tid; idx < LL / 4; idx += 128)
        ((float4*)E_sm)[idx] = ((const float4*)&E_s[b][n][0])[idx];
    for (int idx = tid; idx < HD * LL / 4; idx += 128)
        ((float4*)&W_sm[0][0])[idx] = ((const float4*)&W_s[b][n][0][0])[idx];
    {
        const int4* src = (const int4*)(bmg + (size_t)(b * LL + rowbase) * 32);
        for (int idx = tid; idx < 1024; idx += 128) {
            int4 v = src[idx];
            int row = idx >> 3, w0 = (idx & 7) * 4;
            bm[row][w0 + 0] = (unsigned)v.x;
            bm[row][w0 + 1] = (unsigned)v.y;
            bm[row][w0 + 2] = (unsigned)v.z;
            bm[row][w0 + 3] = (unsigned)v.w;
        }
    }
    __syncthreads();

    int cq = warp;                       // col quarter: words [cq*8, cq*8+8)

    ull acc[4][11];
#pragma unroll
    for (int k = 0; k < 4; k++)
#pragma unroll
        for (int v = 0; v < 11; v++) acc[k][v] = 0ull;

    const ulonglong2* Ep = (const ulonglong2*)E_sm;

    for (int wd0 = 0; wd0 < 8; ++wd0) {
        int wd = cq * 8 + wd0;
        unsigned wr[4];
#pragma unroll
        for (int k = 0; k < 4; k++) wr[k] = bm[k * 32 + lane][wd];
#pragma unroll
        for (int g = 0; g < 8; ++g) {
            int idx = wd * 8 + g;        // ulonglong2 index: cols [idx*4, idx*4+4)
            ull m[4][2];
#pragma unroll
            for (int k = 0; k < 4; k++) {
                unsigned bt = (wr[k] >> (g * 4)) & 0xFu;
                m[k][0] = (ull)((bt & 1u) ? 0x3F800000u : 0u) |
                          ((ull)((bt & 2u) ? 0x3F800000u : 0u) << 32);
                m[k][1] = (ull)((bt & 4u) ? 0x3F800000u : 0u) |
                          ((ull)((bt & 8u) ? 0x3F800000u : 0u) << 32);
            }
            ulonglong2 e = Ep[idx];
#pragma unroll
            for (int k = 0; k < 4; k++) {
                ffma2(acc[k][10], e.x, m[k][0]);
                ffma2(acc[k][10], e.y, m[k][1]);
            }
#pragma unroll
            for (int d = 0; d < HD; ++d) {
                ulonglong2 w = ((const ulonglong2*)W_sm[d])[idx];
#pragma unroll
                for (int k = 0; k < 4; k++) {
                    ffma2(acc[k][d], w.x, m[k][0]);
                    ffma2(acc[k][d], w.y, m[k][1]);
                }
            }
        }
    }

    __syncthreads();   // all warps done READING bm before part[] overwrites it

#pragma unroll
    for (int k = 0; k < 4; k++)
#pragma unroll
        for (int v = 0; v < 11; ++v)
            part[cq][k * 32 + lane][v] = pairsum(acc[k][v]);
    __syncthreads();

    {
        int row = tid;   // 128 threads = 128 rows
        float s[11];
#pragma unroll
        for (int v = 0; v < 11; ++v)
            s[v] = (part[0][row][v] + part[1][row][v]) +
                   (part[2][row][v] + part[3][row][v]);
        float inv = 1.0f / s[10];
        float* attbase = &att_s[b][(size_t)n * LL * HD + (size_t)(rowbase + row) * HD];
#pragma unroll
        for (int d = 0; d < HD; ++d)
            attbase[d] = s[d] * inv;
        inv_s[b][n][rowbase + row] = inv;
    }
}

// ---------------------------------------------------------------------------
// Kernel 3b: SINGLE-PASS alpha write (consumes inv_s from k3a). Warp = row.
// Per float4: 1 LDG.128 E + mask + packed f32x2 muls + 1 STG.128.
// grid (64, NH, B), 512 thr. DRAM-write-bound.
// ---------------------------------------------------------------------------
__global__ void __launch_bounds__(512) k3b_alpha(float* __restrict__ alpha_out) {
    int n = blockIdx.y, b = blockIdx.z;
    int warp = threadIdx.x >> 5, lane = threadIdx.x & 31;
    int row = blockIdx.x * 16 + warp;

    float inv = __ldg(&inv_s[b][n][row]);
    unsigned ib = __float_as_uint(inv);
    ull inv2 = (ull)ib | ((ull)ib << 32);

    const ulonglong2* Ep = (const ulonglong2*)&E_s[b][n][0];
    const unsigned* mrow = bmg + (size_t)(b * LL + row) * 32;
    ulonglong2* arow = (ulonglong2*)(alpha_out + ((size_t)((b * NH + n) * LL) + row) * LL);

#pragma unroll
    for (int it = 0; it < 8; ++it) {
        int c4 = it * 32 + lane;
        ulonglong2 e = Ep[c4];
        unsigned word = __ldg(&mrow[c4 >> 3]);
        unsigned bt = (word >> ((c4 & 7) * 4)) & 0xFu;
        ull m0 = (ull)((bt & 1u) ? 0x3F800000u : 0u) |
                 ((ull)((bt & 2u) ? 0x3F800000u : 0u) << 32);
        ull m1 = (ull)((bt & 4u) ? 0x3F800000u : 0u) |
                 ((ull)((bt & 8u) ? 0x3F800000u : 0u) << 32);
        ulonglong2 o;
        o.x = fmul2(fmul2(e.x, inv2), m0);
        o.y = fmul2(fmul2(e.y, inv2), m1);
        arow[c4] = o;
    }
}

// ---------------------------------------------------------------------------
// Kernel 4: ret[b,o,l] = sum_c wo_w[o,c] * att_flat[b][c*LL+l] + wo_b[o]
// dyn smem: as_[100][36] (14400B) + wsm[64][101] (25856B) = 40256B
// ---------------------------------------------------------------------------
__global__ void __launch_bounds__(128) k4_out(const float* __restrict__ wo_w,
                                              const float* __restrict__ wo_b,
                                              float* __restrict__ out) {
    extern __shared__ __align__(16) char smem4[];
    float (*as_)[36]  = (float(*)[36])smem4;                  // [c][l]
    float (*wsm)[101] = (float(*)[101])(smem4 + 14400);       // [o_local][c] natural

    int lt = blockIdx.x, oh = blockIdx.y, b = blockIdx.z;
    int tid = threadIdx.x;

    for (int idx = tid; idx < 800; idx += 128) {
        int c = idx >> 3, lq = idx & 7;
        float4 v = *(const float4*)&att_s[b][(size_t)c * LL + lt * 32 + lq * 4];
        *(float4*)&as_[c][lq * 4] = v;
    }
    {
        const float4* src = (const float4*)(wo_w + (size_t)oh * 64 * DD);
        for (int f = tid; f < 1600; f += 128) {
            float4 w = src[f];
            int p = f * 4;
#pragma unroll
            for (int k = 0; k < 4; k++) {
                int pk = p + k;
                int ol = pk / DD, c = pk % DD;
                float v = (k == 0) ? w.x : (k == 1) ? w.y : (k == 2) ? w.z : w.w;
                wsm[ol][c] = v;
            }
        }
    }
    __syncthreads();

    int lg = tid >> 4, og = tid & 15;
    int ol0 = og * 4, l0 = lg * 4;

    float acc[4][4];
#pragma unroll
    for (int i = 0; i < 4; i++)
#pragma unroll
        for (int j = 0; j < 4; j++) acc[i][j] = 0.f;

#pragma unroll 4
    for (int c = 0; c < DD; c++) {
        float wa[4];
#pragma unroll
        for (int i = 0; i < 4; i++) wa[i] = wsm[ol0 + i][c];
        float4 av = *(const float4*)&as_[c][l0];
        float aa[4] = {av.x, av.y, av.z, av.w};
#pragma unroll
        for (int i = 0; i < 4; i++)
#pragma unroll
            for (int j = 0; j < 4; j++) acc[i][j] += wa[i] * aa[j];
    }

#pragma unroll
    for (int i = 0; i < 4; i++) {
        int o = oh * 64 + ol0 + i;
        float bias = __ldg(&wo_b[o]);
        float4 ov = make_float4(acc[i][0] + bias, acc[i][1] + bias,
                                acc[i][2] + bias, acc[i][3] + bias);
        *(float4*)&out[((size_t)(b * NHID + o) * LL) + lt * 32 + l0] = ov;
    }
}

// ---------------------------------------------------------------------------
extern "C" void kernel_launch(void* const* d_in, const int* in_sizes, int n_in,
                              void* d_out, int out_size) {
    const float* x       = (const float*)d_in[0];
    const int*   edge    = (const int*)  d_in[1];
    const float* wq_w    = (const float*)d_in[2];
    const float* wq_b    = (const float*)d_in[3];
    const float* wedge_w = (const float*)d_in[4];
    // d_in[5] = wedge_b (cancels in softmax), unused
    const float* wo_w    = (const float*)d_in[6];
    const float* wo_b    = (const float*)d_in[7];

    float* out   = (float*)d_out;
    float* alpha = out + (size_t)BB * NHID * LL;   // ret first, then alpha

    static int inited = 0;
    static cudaStream_t s2;
    static cudaEvent_t evA, evB, evC, evD;
    if (!inited) {
        cudaFuncSetAttribute(k1_q,    cudaFuncAttributeMaxDynamicSharedMemorySize, 35216);
        cudaFuncSetAttribute(k3a_att, cudaFuncAttributeMaxDynamicSharedMemorySize, 69632);
        cudaFuncSetAttribute(k3a_att, cudaFuncAttributePreferredSharedMemoryCarveout, 100);
        cudaFuncSetAttribute(k4_out,  cudaFuncAttributeMaxDynamicSharedMemorySize, 40256);
        cudaStreamCreateWithFlags(&s2, cudaStreamNonBlocking);
        cudaEventCreateWithFlags(&evA, cudaEventDisableTiming);
        cudaEventCreateWithFlags(&evB, cudaEventDisableTiming);
        cudaEventCreateWithFlags(&evC, cudaEventDisableTiming);
        cudaEventCreateWithFlags(&evD, cudaEventDisableTiming);
        inited = 1;
    }

    // front: k0 (mask pack, DRAM-read) on s2 concurrent with k1+k2 (compute)
    cudaEventRecord(evA, 0);
    cudaStreamWaitEvent(s2, evA, 0);
    k0_pack <<<512, 256, 0, s2>>>(edge);
    k1_q    <<<dim3(32, 2, BB),  256, 35216>>>(x, wq_w);
    k2_ew   <<<dim3(8, NH, BB),  128>>>(wedge_w, wq_b);
    cudaEventRecord(evB, s2);
    cudaStreamWaitEvent(0, evB, 0);

    // k3a (compute-bound) serial, then k4 (small) on s2 overlapping k3b (DRAM)
    k3a_att <<<dim3(NH, 8, BB),  128, 69632>>>();

    cudaEventRecord(evC, 0);
    cudaStreamWaitEvent(s2, evC, 0);
    k4_out  <<<dim3(32, 2, BB),  128, 40256, s2>>>(wo_w, wo_b, out);
    k3b_alpha<<<dim3(64, NH, BB), 512>>>(alpha);
    cudaEventRecord(evD, s2);
    cudaStreamWaitEvent(0, evD, 0);
}

// round 14
// speedup vs baseline: 1.1578x; 1.1578x over previous
#include <cuda_runtime.h>

#define LL 1024
#define BB 4
#define NHID 128
#define NH 10
#define HD 10
#define DD 100
#define INV_SQRT_HD 0.31622776601683794f

typedef unsigned long long ull;

// Scratch (device globals: no allocation allowed)
static __device__ float qp_s[2][BB][DD][LL];                  // q partials (h-split)
static __device__ __align__(16) float E_s[BB][NH][LL];        // exp(t) (no max shift)
static __device__ __align__(16) float W_s[BB][NH][HD][LL];    // E * k
// att in the reference's scrambled channel layout: att_flat[b][n*LL*HD + i*HD + d]
static __device__ float att_s[BB][DD * LL];
// packed edge mask: bit k of word w covers col w*32+k; flat [b][row][32 words]
static __device__ __align__(16) unsigned bmg[BB * LL * 32];

__device__ __forceinline__ void ffma2(ull &acc, ull a, ull b) {
    asm("fma.rn.f32x2 %0, %1, %2, %0;" : "+l"(acc) : "l"(a), "l"(b));
}
__device__ __forceinline__ ull fmul2(ull a, ull b) {
    ull r;
    asm("mul.rn.f32x2 %0, %1, %2;" : "=l"(r) : "l"(a), "l"(b));
    return r;
}
__device__ __forceinline__ float pairsum(ull a) {
    return __uint_as_float((unsigned)a) + __uint_as_float((unsigned)(a >> 32));
}

// ---------------------------------------------------------------------------
// Kernel 0: pack edge (4M int32) -> bitmask (128K words). Coalesced + ballot.
// ---------------------------------------------------------------------------
__global__ void __launch_bounds__(256) k0_pack(const int* __restrict__ edge) {
    unsigned t = blockIdx.x * 256 + threadIdx.x;   // 131072 threads
#pragma unroll
    for (int it = 0; it < 32; ++it) {
        unsigned g = it * 131072u + t;
        unsigned word = __ballot_sync(0xffffffffu, edge[g] != 0);
        if ((threadIdx.x & 31) == 0) bmg[g >> 5] = word;
    }
}

// ---------------------------------------------------------------------------
// Kernel 1: q partials. qp[hh][b][c][l] = sum_{h in hh-half} wq_w[c,h]*x[b,h,l]
// grid (32 l-tiles, 2 h-halves, B), 256 thr.
// dyn smem: xs[64][36] (9216B) + wsm[100][65] (26000B) = 35216B
// ---------------------------------------------------------------------------
__global__ void __launch_bounds__(256) k1_q(const float* __restrict__ x,
                                            const float* __restrict__ wq_w) {
    extern __shared__ __align__(16) char smem1[];
    float (*xs)[36]  = (float(*)[36])smem1;                  // [h][l]
    float (*wsm)[65] = (float(*)[65])(smem1 + 9216);         // [c][h] natural, odd pad

    int lt = blockIdx.x, hh = blockIdx.y, b = blockIdx.z;
    int tid = threadIdx.x;

    for (int idx = tid; idx < 512; idx += 256) {
        int h = idx >> 3, lq = idx & 7;
        float4 v = *(const float4*)&x[((size_t)(b * NHID + hh * 64 + h) * LL) + lt * 32 + lq * 4];
        *(float4*)&xs[h][lq * 4] = v;
    }
    for (int f = tid; f < 1600; f += 256) {
        int c = f >> 4, h4 = f & 15;
        float4 w = ((const float4*)wq_w)[c * 32 + hh * 16 + h4];
        wsm[c][h4 * 4 + 0] = w.x;
        wsm[c][h4 * 4 + 1] = w.y;
        wsm[c][h4 * 4 + 2] = w.z;
        wsm[c][h4 * 4 + 3] = w.w;
    }
    __syncthreads();

    int lg = tid >> 5, cg = tid & 31;
    int c0 = cg * 4, l0 = lg * 4;
    int c0c = (c0 > 96) ? 96 : c0;

    float acc[4][4];
#pragma unroll
    for (int i = 0; i < 4; i++)
#pragma unroll
        for (int j = 0; j < 4; j++) acc[i][j] = 0.f;

#pragma unroll 4
    for (int h = 0; h < 64; h++) {
        float wa[4];
#pragma unroll
        for (int i = 0; i < 4; i++) wa[i] = wsm[c0c + i][h];
        float4 xv = *(const float4*)&xs[h][l0];
        float xa[4] = {xv.x, xv.y, xv.z, xv.w};
#pragma unroll
        for (int i = 0; i < 4; i++)
#pragma unroll
            for (int j = 0; j < 4; j++) acc[i][j] += wa[i] * xa[j];
    }

#pragma unroll
    for (int i = 0; i < 4; i++) {
        int c = c0 + i;
        if (c < DD) {
            float4 o = make_float4(acc[i][0], acc[i][1], acc[i][2], acc[i][3]);
            *(float4*)&qp_s[hh][b][c][lt * 32 + l0] = o;
        }
    }
}

// ---------------------------------------------------------------------------
// Kernel 2: E/W. No max subtraction (shift-invariant; |t| small) -> parallel.
// grid (8, NH, B), 128 thr; thread = one l.
// ---------------------------------------------------------------------------
__global__ void __launch_bounds__(128) k2_ew(const float* __restrict__ wedge_w,
                                             const float* __restrict__ wq_b) {
    int n = blockIdx.y, b = blockIdx.z;
    int l = blockIdx.x * 128 + threadIdx.x;

    float qd[HD];
    float t = 0.f;
#pragma unroll
    for (int d = 0; d < HD; d++) {
        int c = n * HD + d;
        qd[d] = qp_s[0][b][c][l] + qp_s[1][b][c][l] + __ldg(&wq_b[c]);
        t += qd[d] * __ldg(&wedge_w[HD + d]);
    }
    t *= INV_SQRT_HD;

    float E = expf(t);
    E_s[b][n][l] = E;
#pragma unroll
    for (int d = 0; d < HD; d++) W_s[b][n][d][l] = E * qd[d];
}

// ---------------------------------------------------------------------------
// Kernel 3 (FUSED): att + inv + alpha write, per (b, n, 128-row tile).
// 256 threads = 8 warps.
// Pass 1 (R7 config): warp w -> col-quarter cq=w>>1, row-half rh=w&1; lane
//   owns TWO rows; E/W LDS.128 broadcasts amortized over 2 rows; bm from smem.
// Combine: deterministic 4-way partial sum -> att_s + invs[] (smem).
// Pass 2: warp w writes rows [w*16, w*16+16): alpha = mask * E * inv.
//   E from smem, mask re-read from L2-resident bmg (so bm smem is dead after
//   pass 1 and part[] overlays it), packed f32x2 muls, STG.128 streams.
// Per-block write phases overlap other blocks' compute phases on the same SM.
// dyn smem: E(4096)+W(40960)+max(bm 16896, part 24576)+invs(512)=70144B
// ---------------------------------------------------------------------------
__global__ void __launch_bounds__(256) k3_fused(float* __restrict__ alpha_out) {
    extern __shared__ __align__(16) char smem3[];
    float* E_sm = (float*)smem3;                                   // [1024]
    float (*W_sm)[LL] = (float(*)[LL])(smem3 + 4096);              // [10][1024]
    unsigned (*bm)[33] = (unsigned(*)[33])(smem3 + 45056);         // [128][33]
    float (*part)[128][12] = (float(*)[128][12])(smem3 + 45056);   // [4][128][12] OVERLAY
    float* invs = (float*)(smem3 + 69632);                         // [128]

    int n = blockIdx.x, tile = blockIdx.y, b = blockIdx.z;
    int tid = threadIdx.x, warp = tid >> 5, lane = tid & 31;
    int rowbase = tile * 128;

    for (int idx = tid; idx < LL / 4; idx += 256)
        ((float4*)E_sm)[idx] = ((const float4*)&E_s[b][n][0])[idx];
    for (int idx = tid; idx < HD * LL / 4; idx += 256)
        ((float4*)&W_sm[0][0])[idx] = ((const float4*)&W_s[b][n][0][0])[idx];
    {
        const int4* src = (const int4*)(bmg + (size_t)(b * LL + rowbase) * 32);
        for (int idx = tid; idx < 1024; idx += 256) {
            int4 v = src[idx];
            int row = idx >> 3, w0 = (idx & 7) * 4;
            bm[row][w0 + 0] = (unsigned)v.x;
            bm[row][w0 + 1] = (unsigned)v.y;
            bm[row][w0 + 2] = (unsigned)v.z;
            bm[row][w0 + 3] = (unsigned)v.w;
        }
    }
    __syncthreads();

    // ---- pass 1 ----
    int cq = warp >> 1;                 // col quarter: words [cq*8, cq*8+8)
    int rh = warp & 1;                  // row half
    int r0 = rh * 64 + lane, r1 = r0 + 32;

    ull accA[11], accB[11];
#pragma unroll
    for (int v = 0; v < 11; v++) { accA[v] = 0ull; accB[v] = 0ull; }

    const ulonglong2* Ep = (const ulonglong2*)E_sm;

    for (int wd = cq * 8; wd < cq * 8 + 8; ++wd) {
        unsigned wordA = bm[r0][wd];
        unsigned wordB = bm[r1][wd];
#pragma unroll
        for (int g = 0; g < 8; ++g) {
            int idx = wd * 8 + g;       // ulonglong2 index: cols [idx*4, idx*4+4)
            unsigned bA = (wordA >> (g * 4)) & 0xFu;
            unsigned bB = (wordB >> (g * 4)) & 0xFu;
            ull mA0 = (ull)((bA & 1u) ? 0x3F800000u : 0u) |
                      ((ull)((bA & 2u) ? 0x3F800000u : 0u) << 32);
            ull mA1 = (ull)((bA & 4u) ? 0x3F800000u : 0u) |
                      ((ull)((bA & 8u) ? 0x3F800000u : 0u) << 32);
            ull mB0 = (ull)((bB & 1u) ? 0x3F800000u : 0u) |
                      ((ull)((bB & 2u) ? 0x3F800000u : 0u) << 32);
            ull mB1 = (ull)((bB & 4u) ? 0x3F800000u : 0u) |
                      ((ull)((bB & 8u) ? 0x3F800000u : 0u) << 32);
            ulonglong2 e = Ep[idx];
            ffma2(accA[10], e.x, mA0);
            ffma2(accA[10], e.y, mA1);
            ffma2(accB[10], e.x, mB0);
            ffma2(accB[10], e.y, mB1);
#pragma unroll
            for (int d = 0; d < HD; ++d) {
                ulonglong2 w = ((const ulonglong2*)W_sm[d])[idx];
                ffma2(accA[d], w.x, mA0);
                ffma2(accA[d], w.y, mA1);
                ffma2(accB[d], w.x, mB0);
                ffma2(accB[d], w.y, mB1);
            }
        }
    }

    __syncthreads();   // all warps done READING bm before part[] overwrites it

#pragma unroll
    for (int v = 0; v < 11; ++v) {
        part[cq][r0][v] = pairsum(accA[v]);
        part[cq][r1][v] = pairsum(accB[v]);
    }
    __syncthreads();

    if (tid < 128) {
        int row = tid;
        float s[11];
#pragma unroll
        for (int v = 0; v < 11; ++v)
            s[v] = (part[0][row][v] + part[1][row][v]) +
                   (part[2][row][v] + part[3][row][v]);
        float inv = 1.0f / s[10];
        float* attbase = &att_s[b][(size_t)n * LL * HD + (size_t)(rowbase + row) * HD];
#pragma unroll
        for (int d = 0; d < HD; ++d)
            attbase[d] = s[d] * inv;
        invs[row] = inv;
    }
    __syncthreads();

    // ---- pass 2: alpha streaming (warp = 16 rows) ----
    for (int r = warp * 16; r < warp * 16 + 16; ++r) {
        float inv = invs[r];
        unsigned ib = __float_as_uint(inv);
        ull inv2 = (ull)ib | ((ull)ib << 32);
        const unsigned* mrow = bmg + (size_t)(b * LL + rowbase + r) * 32;   // L2-resident
        ulonglong2* arow = (ulonglong2*)(alpha_out +
                           ((size_t)((b * NH + n) * LL) + rowbase + r) * LL);
#pragma unroll
        for (int it = 0; it < 8; ++it) {
            int c4 = it * 32 + lane;
            ulonglong2 e = Ep[c4];
            unsigned word = __ldg(&mrow[c4 >> 3]);
            unsigned bt = (word >> ((c4 & 7) * 4)) & 0xFu;
            ull m0 = (ull)((bt & 1u) ? 0x3F800000u : 0u) |
                     ((ull)((bt & 2u) ? 0x3F800000u : 0u) << 32);
            ull m1 = (ull)((bt & 4u) ? 0x3F800000u : 0u) |
                     ((ull)((bt & 8u) ? 0x3F800000u : 0u) << 32);
            ulonglong2 o;
            o.x = fmul2(fmul2(e.x, inv2), m0);
            o.y = fmul2(fmul2(e.y, inv2), m1);
            arow[c4] = o;
        }
    }
}

// ---------------------------------------------------------------------------
// Kernel 4: ret[b,o,l] = sum_c wo_w[o,c] * att_flat[b][c*LL+l] + wo_b[o]
// dyn smem: as_[100][36] (14400B) + wsm[64][101] (25856B) = 40256B
// ---------------------------------------------------------------------------
__global__ void __launch_bounds__(128) k4_out(const float* __restrict__ wo_w,
                                              const float* __restrict__ wo_b,
                                              float* __restrict__ out) {
    extern __shared__ __align__(16) char smem4[];
    float (*as_)[36]  = (float(*)[36])smem4;                  // [c][l]
    float (*wsm)[101] = (float(*)[101])(smem4 + 14400);       // [o_local][c] natural

    int lt = blockIdx.x, oh = blockIdx.y, b = blockIdx.z;
    int tid = threadIdx.x;

    for (int idx = tid; idx < 800; idx += 128) {
        int c = idx >> 3, lq = idx & 7;
        float4 v = *(const float4*)&att_s[b][(size_t)c * LL + lt * 32 + lq * 4];
        *(float4*)&as_[c][lq * 4] = v;
    }
    {
        const float4* src = (const float4*)(wo_w + (size_t)oh * 64 * DD);
        for (int f = tid; f < 1600; f += 128) {
            float4 w = src[f];
            int p = f * 4;
#pragma unroll
            for (int k = 0; k < 4; k++) {
                int pk = p + k;
                int ol = pk / DD, c = pk % DD;
                float v = (k == 0) ? w.x : (k == 1) ? w.y : (k == 2) ? w.z : w.w;
                wsm[ol][c] = v;
            }
        }
    }
    __syncthreads();

    int lg = tid >> 4, og = tid & 15;
    int ol0 = og * 4, l0 = lg * 4;

    float acc[4][4];
#pragma unroll
    for (int i = 0; i < 4; i++)
#pragma unroll
        for (int j = 0; j < 4; j++) acc[i][j] = 0.f;

#pragma unroll 4
    for (int c = 0; c < DD; c++) {
        float wa[4];
#pragma unroll
        for (int i = 0; i < 4; i++) wa[i] = wsm[ol0 + i][c];
        float4 av = *(const float4*)&as_[c][l0];
        float aa[4] = {av.x, av.y, av.z, av.w};
#pragma unroll
        for (int i = 0; i < 4; i++)
#pragma unroll
            for (int j = 0; j < 4; j++) acc[i][j] += wa[i] * aa[j];
    }

#pragma unroll
    for (int i = 0; i < 4; i++) {
        int o = oh * 64 + ol0 + i;
        float bias = __ldg(&wo_b[o]);
        float4 ov = make_float4(acc[i][0] + bias, acc[i][1] + bias,
                                acc[i][2] + bias, acc[i][3] + bias);
        *(float4*)&out[((size_t)(b * NHID + o) * LL) + lt * 32 + l0] = ov;
    }
}

// ---------------------------------------------------------------------------
extern "C" void kernel_launch(void* const* d_in, const int* in_sizes, int n_in,
                              void* d_out, int out_size) {
    const float* x       = (const float*)d_in[0];
    const int*   edge    = (const int*)  d_in[1];
    const float* wq_w    = (const float*)d_in[2];
    const float* wq_b    = (const float*)d_in[3];
    const float* wedge_w = (const float*)d_in[4];
    // d_in[5] = wedge_b (cancels in softmax), unused
    const float* wo_w    = (const float*)d_in[6];
    const float* wo_b    = (const float*)d_in[7];

    float* out   = (float*)d_out;
    float* alpha = out + (size_t)BB * NHID * LL;   // ret first, then alpha

    static int inited = 0;
    static cudaStream_t s2;
    static cudaEvent_t evA, evB;
    if (!inited) {
        cudaFuncSetAttribute(k1_q,     cudaFuncAttributeMaxDynamicSharedMemorySize, 35216);
        cudaFuncSetAttribute(k3_fused, cudaFuncAttributeMaxDynamicSharedMemorySize, 70144);
        cudaFuncSetAttribute(k3_fused, cudaFuncAttributePreferredSharedMemoryCarveout, 100);
        cudaFuncSetAttribute(k4_out,   cudaFuncAttributeMaxDynamicSharedMemorySize, 40256);
        cudaStreamCreateWithFlags(&s2, cudaStreamNonBlocking);
        cudaEventCreateWithFlags(&evA, cudaEventDisableTiming);
        cudaEventCreateWithFlags(&evB, cudaEventDisableTiming);
        inited = 1;
    }

    // front: k0 (mask pack, DRAM-read) on s2 concurrent with k1+k2 (compute)
    cudaEventRecord(evA, 0);
    cudaStreamWaitEvent(s2, evA, 0);
    k0_pack <<<512, 256, 0, s2>>>(edge);
    k1_q    <<<dim3(32, 2, BB),  256, 35216>>>(x, wq_w);
    k2_ew   <<<dim3(8, NH, BB),  128>>>(wedge_w, wq_b);
    cudaEventRecord(evB, s2);
    cudaStreamWaitEvent(0, evB, 0);

    // fused attention: compute + alpha write overlap across blocks per SM
    k3_fused<<<dim3(NH, 8, BB), 256, 70144>>>(alpha);
    k4_out  <<<dim3(32, 2, BB), 128, 40256>>>(wo_w, wo_b, out);
}